// round 14
// baseline (speedup 1.0000x reference)
#include <cuda_runtime.h>
#include <cuda_fp16.h>
#include <cstdint>

#define N_NODES 50000
#define K_NBR 16
#define D 256
#define LN_EPS 1e-5f
#define SLAB 64
#define NSLAB ((N_NODES + SLAB - 1) / SLAB)   // 782
#define NGATHER 148
#define NTOTAL (NGATHER + 148)                 // 296 blocks, 2/SM

// ---------------------------------------------------------------------------
// Device-global scratch (allocation-free rule)
// ---------------------------------------------------------------------------
__device__ __align__(16) __half g_wt[D * D];          // W^T fp16 [n][k]
__device__ __align__(16) __half g_fh[N_NODES * D];    // features fp16 (25.6 MB)
__device__ __align__(16) __half g_x[N_NODES * D];     // gathered x fp16 (25.6 MB)
__device__ int g_done[NSLAB];
__device__ int g_gnext;
__device__ int g_mnext;

// ---------------------------------------------------------------------------
// PTX helpers (baseline sm_80+ — must compile at virtual compute_103)
// ---------------------------------------------------------------------------
__device__ __forceinline__ uint32_t smem_to_u32(const void* p) {
    uint32_t a;
    asm("{ .reg .u64 t; cvta.to.shared.u64 t, %1; cvt.u32.u64 %0, t; }"
        : "=r"(a) : "l"(p));
    return a;
}

#define CP_ASYNC16(dst, src, szz) \
    asm volatile("cp.async.cg.shared.global [%0], [%1], 16, %2;" \
                 :: "r"(dst), "l"(src), "r"(szz) : "memory")
#define CP_COMMIT() asm volatile("cp.async.commit_group;" ::: "memory")
#define CP_WAIT(n)  asm volatile("cp.async.wait_group %0;" :: "n"(n) : "memory")

#define LDSM_X4(d, addr) \
    asm volatile("ldmatrix.sync.aligned.m8n8.x4.shared.b16 {%0,%1,%2,%3}, [%4];" \
                 : "=r"((d)[0]), "=r"((d)[1]), "=r"((d)[2]), "=r"((d)[3]) \
                 : "r"(addr))

__device__ __forceinline__ void mma16816(float c[4], const uint32_t a[4],
                                         uint32_t b0, uint32_t b1) {
    asm volatile(
        "mma.sync.aligned.m16n8k16.row.col.f32.f16.f16.f32 "
        "{%0,%1,%2,%3}, {%4,%5,%6,%7}, {%8,%9}, {%0,%1,%2,%3};"
        : "+f"(c[0]), "+f"(c[1]), "+f"(c[2]), "+f"(c[3])
        : "r"(a[0]), "r"(a[1]), "r"(a[2]), "r"(a[3]), "r"(b0), "r"(b1));
}

__device__ __forceinline__ float2 u2f2(uint32_t u) {
    __half2 h = *reinterpret_cast<__half2*>(&u);
    return __half22float2(h);
}
__device__ __forceinline__ uint32_t f2u(float a, float b) {
    __half2 h = __floats2half2_rn(a, b);
    return *reinterpret_cast<uint32_t*>(&h);
}

#define NANOSLEEP() asm volatile("nanosleep.u32 200;")

// ---------------------------------------------------------------------------
// SMEM layout (88 KB; 2 blocks/SM)
//   gemm role : stage s (s=0,1) @ s*40960: A 8 KB, B @ +8192 32 KB
//   gather role: SNB@0 (4 KB), SW@4096 (4 KB)   (reuses A region)
// ---------------------------------------------------------------------------
#define OFF_A(s)   ((uint32_t)(s) * 40960u)
#define OFF_B(s)   ((uint32_t)(s) * 40960u + 8192u)
#define OFF_SNB    0
#define OFF_SW     4096
#define OFF_BIAS   81920
#define OFF_GAMMA  82944
#define OFF_BETA   83968
#define OFF_RED    84992   // float2 red[64][4] = 2 KB
#define OFF_STAT   87040   // float2 stat[64]   = 512 B
#define OFF_CLAIM  87552   // int
#define SMEM_TOTAL 87808

// ---------------------------------------------------------------------------
// Kernel 0a: W -> W^T fp16 (coalesced transpose) + zero sync state
// ---------------------------------------------------------------------------
__global__ __launch_bounds__(256) void prep_w(const float* __restrict__ W) {
    const int flat = (blockIdx.y * 8 + blockIdx.x) * 256
                   + threadIdx.y * 32 + threadIdx.x;
    if (flat < NSLAB)      g_done[flat] = 0;
    if (flat == NSLAB)     g_gnext = 0;
    if (flat == NSLAB + 1) g_mnext = 0;

    __shared__ float tile[32][33];
    const int bx = blockIdx.x * 32;   // n tile
    const int by = blockIdx.y * 32;   // k tile
    const int tx = threadIdx.x;
    const int ty = threadIdx.y;

#pragma unroll
    for (int i = 0; i < 4; i++)
        tile[ty + i * 8][tx] = W[(by + ty + i * 8) * D + bx + tx];
    __syncthreads();
#pragma unroll
    for (int i = 0; i < 4; i++) {
        const int n = bx + ty + i * 8;
        const int k = by + tx;
        g_wt[n * D + k] = __float2half_rn(tile[tx][ty + i * 8]);
    }
}

// ---------------------------------------------------------------------------
// Kernel 0b: features fp32 -> fp16 (streaming convert; 12.8M elems)
// ---------------------------------------------------------------------------
__global__ __launch_bounds__(256) void prep_feat(const float* __restrict__ f) {
    const size_t i = (size_t)blockIdx.x * 256 + threadIdx.x;   // float4 index
    const float4 v = ((const float4*)f)[i];
    uint2 o;
    o.x = f2u(v.x, v.y);
    o.y = f2u(v.z, v.w);
    ((uint2*)g_fh)[i] = o;
}

// ---------------------------------------------------------------------------
// Fused overlap kernel: 296 blocks, all co-resident (2/SM).
//   blocks 0..147   : persistent gather producers (slab queue, in order)
//   blocks 148..295 : persistent gemm+LN consumers (slab queue, in order)
// ---------------------------------------------------------------------------
__global__ __launch_bounds__(256, 2) void fused_overlap(
    const int* __restrict__ neighbors,     // int32 (JAX x64-off downcast)
    const float* __restrict__ weights,
    const float* __restrict__ bias,
    const float* __restrict__ gamma,
    const float* __restrict__ beta,
    float* __restrict__ out)
{
    extern __shared__ char smem[];
    const uint32_t su = smem_to_u32(smem);
    const int tid = threadIdx.x;
    int* claim = (int*)(smem + OFF_CLAIM);

    if (blockIdx.x < NGATHER) {
        // ================= GATHER PRODUCER =================
        float* swp = (float*)(smem + OFF_SW);
        int*   snp = (int*)(smem + OFF_SNB);
        const uint4* __restrict__ f4 = (const uint4*)g_fh;
        const int nl8 = tid >> 5;   // node group 0..7
        const int t   = tid & 31;   // uint4 lane (8 halves)

        for (;;) {
            if (tid == 0) *claim = atomicAdd(&g_gnext, 1);
            __syncthreads();
            const int u = *claim;
            __syncthreads();
            if (u >= NSLAB) break;
            const int rb = u * SLAB;

            // tables
            for (int i = tid; i < SLAB * K_NBR; i += 256) {
                const int nl = i >> 4, kk = i & 15;
                const int gn = rb + nl;
                float w = 0.f; int nb = 0;
                if (gn < N_NODES) {
                    w  = weights[gn * K_NBR + kk];
                    nb = neighbors[gn * K_NBR + kk];
                }
                swp[i] = w; snp[i] = nb;
            }
            __syncthreads();
            if (tid < SLAB) {
                float ws = 0.f;
#pragma unroll
                for (int k = 0; k < K_NBR; k++) ws += swp[tid * K_NBR + k];
                const bool z = (ws == 0.f);
                const float inv = z ? 0.f : 1.f / ws;
#pragma unroll
                for (int k = 0; k < K_NBR; k++)
                    swp[tid * K_NBR + k] = z ? (1.f / (float)K_NBR)
                                             : swp[tid * K_NBR + k] * inv;
            }
            __syncthreads();

            // gather: 8 nodes concurrent x 8 batches; thread owns 8 cols
            for (int batch = 0; batch < 8; batch++) {
                const int nl = batch * 8 + nl8;
                const int node = rb + nl;
                if (node < N_NODES) {
                    const float* wv = swp + nl * K_NBR;
                    const int*   nv = snp + nl * K_NBR;
                    float2 acc[4] = {{0.f,0.f},{0.f,0.f},{0.f,0.f},{0.f,0.f}};
#pragma unroll
                    for (int k = 0; k < K_NBR; k++) {
                        const float w = wv[k];
                        const uint4 v = f4[(size_t)nv[k] * 32 + t];
                        float2 f;
                        f = u2f2(v.x); acc[0].x += w * f.x; acc[0].y += w * f.y;
                        f = u2f2(v.y); acc[1].x += w * f.x; acc[1].y += w * f.y;
                        f = u2f2(v.z); acc[2].x += w * f.x; acc[2].y += w * f.y;
                        f = u2f2(v.w); acc[3].x += w * f.x; acc[3].y += w * f.y;
                    }
                    uint4 o;
                    o.x = f2u(acc[0].x, acc[0].y);
                    o.y = f2u(acc[1].x, acc[1].y);
                    o.z = f2u(acc[2].x, acc[2].y);
                    o.w = f2u(acc[3].x, acc[3].y);
                    ((uint4*)g_x)[(size_t)node * 32 + t] = o;
                }
            }
            __threadfence();
            __syncthreads();
            if (tid == 0) *(volatile int*)&g_done[u] = 1;
            __syncthreads();
        }
        return;
    }

    // ================= GEMM + LAYERNORM CONSUMER =================
    const int warp = tid >> 5;
    const int lid  = tid & 31;
    const int wr   = warp >> 2;   // 0..1 : rows wr*32..+31
    const int wc   = warp & 3;    // 0..3 : cols wc*64..+63
    const int grp  = lid >> 3;
    const int idx  = lid & 7;

    if (tid < D) {
        ((float*)(smem + OFF_BIAS))[tid]  = bias[tid];
        ((float*)(smem + OFF_GAMMA))[tid] = gamma[tid];
        ((float*)(smem + OFF_BETA))[tid]  = beta[tid];
    }
    const float* bias_s  = (const float*)(smem + OFF_BIAS);
    const float* gamma_s = (const float*)(smem + OFF_GAMMA);
    const float* beta_s  = (const float*)(smem + OFF_BETA);
    float2* red  = (float2*)(smem + OFF_RED);
    float2* stat = (float2*)(smem + OFF_STAT);

    const int a_kh = grp >> 1;
    uint32_t a_base[2];
#pragma unroll
    for (int mt = 0; mt < 2; mt++)
        a_base[mt] = (uint32_t)((wr * 32 + mt * 16 + (grp & 1) * 8 + idx) * 128);
    const int b_kh = grp & 1;
    uint32_t b_base[4];
#pragma unroll
    for (int p = 0; p < 4; p++)
        b_base[p] = (uint32_t)((wc * 64 + p * 16 + (grp >> 1) * 8 + idx) * 128);
    const uint32_t xorv = (uint32_t)(idx * 16);

    for (;;) {
        if (tid == 0) *claim = atomicAdd(&g_mnext, 1);
        __syncthreads();
        const int j = *claim;
        __syncthreads();
        if (j >= NSLAB) break;
        const int rb = j * SLAB;

        if (tid == 0)
            while (*(volatile int*)&g_done[j] == 0) NANOSLEEP();
        __syncthreads();
        __threadfence();   // acquire before reading x

        float acc[2][8][4];
#pragma unroll
        for (int mt = 0; mt < 2; mt++)
#pragma unroll
            for (int nt = 0; nt < 8; nt++)
#pragma unroll
                for (int q = 0; q < 4; q++) acc[mt][nt][q] = 0.f;

        // ---- stage chunk 0 into stage 0 ----
#pragma unroll
        for (int i = 0; i < 2; i++) {          // A: 64 rows x 8 x 16B
            const int e = i * 256 + tid;
            const int row = e >> 3, u2 = e & 7;
            const uint32_t sw =
                (uint32_t)(row * 128 + u2 * 16) ^ (uint32_t)((row & 7) * 16);
            const int gr = rb + row;
            const int sz = (gr < N_NODES) ? 16 : 0;
            CP_ASYNC16(su + OFF_A(0) + sw,
                       (const char*)&g_x[(size_t)gr * D + u2 * 8], sz);
        }
#pragma unroll
        for (int i = 0; i < 8; i++) {          // B: 256 n x 8 x 16B
            const int e = i * 256 + tid;
            const int n = e >> 3, u2 = e & 7;
            const uint32_t sw =
                (uint32_t)(n * 128 + u2 * 16) ^ (uint32_t)((n & 7) * 16);
            CP_ASYNC16(su + OFF_B(0) + sw,
                       (const char*)&g_wt[(size_t)n * D + u2 * 8], 16);
        }
        CP_COMMIT();

        for (int c = 0; c < 4; c++) {
            if (c < 3) {
                const int s = (c + 1) & 1;
#pragma unroll
                for (int i = 0; i < 2; i++) {
                    const int e = i * 256 + tid;
                    const int row = e >> 3, u2 = e & 7;
                    const uint32_t sw =
                        (uint32_t)(row * 128 + u2 * 16) ^ (uint32_t)((row & 7) * 16);
                    const int gr = rb + row;
                    const int sz = (gr < N_NODES) ? 16 : 0;
                    CP_ASYNC16(su + OFF_A(s) + sw,
                               (const char*)&g_x[(size_t)gr * D + (c + 1) * 64 + u2 * 8], sz);
                }
#pragma unroll
                for (int i = 0; i < 8; i++) {
                    const int e = i * 256 + tid;
                    const int n = e >> 3, u2 = e & 7;
                    const uint32_t sw =
                        (uint32_t)(n * 128 + u2 * 16) ^ (uint32_t)((n & 7) * 16);
                    CP_ASYNC16(su + OFF_B(s) + sw,
                               (const char*)&g_wt[(size_t)n * D + (c + 1) * 64 + u2 * 8], 16);
                }
                CP_COMMIT();
                CP_WAIT(1);
            } else {
                CP_WAIT(0);
            }
            __syncthreads();

            const uint32_t abase = su + OFF_A(c & 1);
            const uint32_t bbase = su + OFF_B(c & 1);

#pragma unroll
            for (int ks = 0; ks < 4; ks++) {
                const uint32_t xa = ((uint32_t)(ks * 32 + a_kh * 16)) ^ xorv;
                const uint32_t xb = ((uint32_t)(ks * 32 + b_kh * 16)) ^ xorv;

                uint32_t ah[2][4];
#pragma unroll
                for (int mt = 0; mt < 2; mt++)
                    LDSM_X4(ah[mt], abase + a_base[mt] + xa);
#pragma unroll
                for (int p = 0; p < 4; p++) {
                    uint32_t bh[4];
                    LDSM_X4(bh, bbase + b_base[p] + xb);
#pragma unroll
                    for (int h = 0; h < 2; h++) {
                        const int nt = p * 2 + h;
                        const uint32_t b0 = bh[h * 2], b1 = bh[h * 2 + 1];
#pragma unroll
                        for (int mt = 0; mt < 2; mt++)
                            mma16816(acc[mt][nt], ah[mt], b0, b1);
                    }
                }
            }
            __syncthreads();   // stage c&1 free for chunk c+2
        }

        // ---- epilogue: bias + LayerNorm + affine ----
#pragma unroll
        for (int mt = 0; mt < 2; mt++)
#pragma unroll
            for (int nt = 0; nt < 8; nt++) {
                const int col = wc * 64 + nt * 8 + (lid & 3) * 2;
                acc[mt][nt][0] += bias_s[col];
                acc[mt][nt][1] += bias_s[col + 1];
                acc[mt][nt][2] += bias_s[col];
                acc[mt][nt][3] += bias_s[col + 1];
            }

        float s1[4], s2[4];
#pragma unroll
        for (int mt = 0; mt < 2; mt++) {
            float a1 = 0.f, a2 = 0.f, b1 = 0.f, b2 = 0.f;
#pragma unroll
            for (int nt = 0; nt < 8; nt++) {
                a1 += acc[mt][nt][0] + acc[mt][nt][1];
                a2 += acc[mt][nt][0] * acc[mt][nt][0] + acc[mt][nt][1] * acc[mt][nt][1];
                b1 += acc[mt][nt][2] + acc[mt][nt][3];
                b2 += acc[mt][nt][2] * acc[mt][nt][2] + acc[mt][nt][3] * acc[mt][nt][3];
            }
            s1[mt * 2] = a1;     s2[mt * 2] = a2;
            s1[mt * 2 + 1] = b1; s2[mt * 2 + 1] = b2;
        }
#pragma unroll
        for (int z = 1; z <= 2; z <<= 1)
#pragma unroll
            for (int i = 0; i < 4; i++) {
                s1[i] += __shfl_xor_sync(0xffffffffu, s1[i], z);
                s2[i] += __shfl_xor_sync(0xffffffffu, s2[i], z);
            }

        if ((lid & 3) == 0) {
            const int g = lid >> 2;
#pragma unroll
            for (int mt = 0; mt < 2; mt++)
#pragma unroll
                for (int h = 0; h < 2; h++) {
                    const int row = wr * 32 + mt * 16 + h * 8 + g;
                    red[row * 4 + wc] = make_float2(s1[mt * 2 + h], s2[mt * 2 + h]);
                }
        }
        __syncthreads();

        if (tid < SLAB) {
            float t1 = 0.f, t2 = 0.f;
#pragma unroll
            for (int w = 0; w < 4; w++) {
                const float2 v = red[tid * 4 + w];
                t1 += v.x; t2 += v.y;
            }
            const float mean = t1 * (1.f / (float)D);
            const float var  = t2 * (1.f / (float)D) - mean * mean;
            stat[tid] = make_float2(mean, rsqrtf(var + LN_EPS));
        }
        __syncthreads();

        const int g = lid >> 2;
#pragma unroll
        for (int mt = 0; mt < 2; mt++) {
            const int r0 = wr * 32 + mt * 16 + g;
            const int r1 = r0 + 8;
            const float2 st0 = stat[r0];
            const float2 st1 = stat[r1];
#pragma unroll
            for (int nt = 0; nt < 8; nt++) {
                const int col = wc * 64 + nt * 8 + (lid & 3) * 2;
                const float gm0 = gamma_s[col], gm1 = gamma_s[col + 1];
                const float bt0 = beta_s[col],  bt1 = beta_s[col + 1];
                if (rb + r0 < N_NODES) {
                    float2 o;
                    o.x = (acc[mt][nt][0] - st0.x) * st0.y * gm0 + bt0;
                    o.y = (acc[mt][nt][1] - st0.x) * st0.y * gm1 + bt1;
                    *(float2*)&out[(size_t)(rb + r0) * D + col] = o;
                }
                if (rb + r1 < N_NODES) {
                    float2 o;
                    o.x = (acc[mt][nt][2] - st1.x) * st1.y * gm0 + bt0;
                    o.y = (acc[mt][nt][3] - st1.x) * st1.y * gm1 + bt1;
                    *(float2*)&out[(size_t)(rb + r1) * D + col] = o;
                }
            }
        }
        __syncthreads();   // protect red/stat/claim before next slab
    }
}

// ---------------------------------------------------------------------------
// Launch
// ---------------------------------------------------------------------------
extern "C" void kernel_launch(void* const* d_in, const int* in_sizes, int n_in,
                              void* d_out, int out_size)
{
    const float* features  = (const float*)d_in[0];
    const int*   neighbors = (const int*)d_in[1];
    const float* weights   = (const float*)d_in[2];
    const float* W         = (const float*)d_in[3];
    const float* bias      = (const float*)d_in[4];
    const float* gamma     = (const float*)d_in[5];
    const float* beta      = (const float*)d_in[6];
    float*       out       = (float*)d_out;

    cudaFuncSetAttribute(fused_overlap,
                         cudaFuncAttributeMaxDynamicSharedMemorySize, SMEM_TOTAL);

    prep_w<<<dim3(8, 8), dim3(32, 8)>>>(W);
    prep_feat<<<(N_NODES * D / 4) / 256, 256>>>(features);
    fused_overlap<<<NTOTAL, 256, SMEM_TOTAL>>>(
        neighbors, weights, bias, gamma, beta, out);
}

// round 15
// speedup vs baseline: 1.3286x; 1.3286x over previous
#include <cuda_runtime.h>
#include <cuda_fp16.h>
#include <cstdint>

#define N_NODES 50000
#define K_NBR 16
#define D 256
#define LN_EPS 1e-5f
#define MROWS 128
#define NBLOCKS ((N_NODES + MROWS - 1) / MROWS)   // 391
#define FEAT_BLOCKS 12500                          // 3.2M float4 / 256

// ---------------------------------------------------------------------------
// Device-global scratch (allocation-free rule)
// ---------------------------------------------------------------------------
__device__ __align__(16) __half g_wt[D * D];          // W^T fp16 [n][k]
__device__ __align__(16) __half g_fh[N_NODES * D];    // features fp16 (25.6 MB)
__device__ __align__(16) __half g_x[N_NODES * D];     // gathered x fp16 (25.6 MB)

// ---------------------------------------------------------------------------
// PTX helpers (baseline sm_80+ — must compile at virtual compute_103)
// ---------------------------------------------------------------------------
__device__ __forceinline__ uint32_t smem_to_u32(const void* p) {
    uint32_t a;
    asm("{ .reg .u64 t; cvta.to.shared.u64 t, %1; cvt.u32.u64 %0, t; }"
        : "=r"(a) : "l"(p));
    return a;
}

#define CP_ASYNC16(dst, src, szz) \
    asm volatile("cp.async.cg.shared.global [%0], [%1], 16, %2;" \
                 :: "r"(dst), "l"(src), "r"(szz) : "memory")
#define CP_COMMIT() asm volatile("cp.async.commit_group;" ::: "memory")
#define CP_WAIT(n)  asm volatile("cp.async.wait_group %0;" :: "n"(n) : "memory")

#define LDSM_X4(d, addr) \
    asm volatile("ldmatrix.sync.aligned.m8n8.x4.shared.b16 {%0,%1,%2,%3}, [%4];" \
                 : "=r"((d)[0]), "=r"((d)[1]), "=r"((d)[2]), "=r"((d)[3]) \
                 : "r"(addr))

__device__ __forceinline__ void mma16816(float c[4], const uint32_t a[4],
                                         uint32_t b0, uint32_t b1) {
    asm volatile(
        "mma.sync.aligned.m16n8k16.row.col.f32.f16.f16.f32 "
        "{%0,%1,%2,%3}, {%4,%5,%6,%7}, {%8,%9}, {%0,%1,%2,%3};"
        : "+f"(c[0]), "+f"(c[1]), "+f"(c[2]), "+f"(c[3])
        : "r"(a[0]), "r"(a[1]), "r"(a[2]), "r"(a[3]), "r"(b0), "r"(b1));
}

__device__ __forceinline__ float2 u2f2(uint32_t u) {
    __half2 h = *reinterpret_cast<__half2*>(&u);
    return __half22float2(h);
}
__device__ __forceinline__ uint32_t f2u(float a, float b) {
    __half2 h = __floats2half2_rn(a, b);
    return *reinterpret_cast<uint32_t*>(&h);
}

// ---------------------------------------------------------------------------
// GEMM SMEM layout (200 KB, 1 CTA/SM)
//   A chunk c @ c*16384          (128 rows x 128 B, swizzled)  4 x 16 KB
//   B chunk c @ 65536 + c*32768  (256 n x 128 B, swizzled)     4 x 32 KB
// ---------------------------------------------------------------------------
#define OFF_A(c)   ((uint32_t)(c) * 16384u)
#define OFF_B(c)   (65536u + (uint32_t)(c) * 32768u)
#define OFF_BIAS   196608
#define OFF_GAMMA  197632
#define OFF_BETA   198656
#define OFF_RED    199680   // float2 red[128][4] = 4 KB
#define OFF_STAT   203776   // float2 stat[128]   = 1 KB
#define SMEM_TOTAL 204800

// ---------------------------------------------------------------------------
// Kernel 0: combined prep.
//   blocks [0, FEAT_BLOCKS)          : features fp32 -> fp16 streaming convert
//   blocks [FEAT_BLOCKS, +64)        : W [D,D] -> W^T fp16 (smem transpose)
// ---------------------------------------------------------------------------
__global__ __launch_bounds__(256) void prep_all(const float* __restrict__ f,
                                                const float* __restrict__ W)
{
    if (blockIdx.x < FEAT_BLOCKS) {
        const size_t i = (size_t)blockIdx.x * 256 + threadIdx.x;   // float4 idx
        const float4 v = ((const float4*)f)[i];
        uint2 o;
        o.x = f2u(v.x, v.y);
        o.y = f2u(v.z, v.w);
        ((uint2*)g_fh)[i] = o;
        return;
    }

    __shared__ float tile[32][33];
    const int tno = blockIdx.x - FEAT_BLOCKS;   // 0..63
    const int bx = (tno & 7) * 32;   // n tile
    const int by = (tno >> 3) * 32;  // k tile
    const int tx = threadIdx.x & 31;
    const int ty = threadIdx.x >> 5; // 0..7

#pragma unroll
    for (int i = 0; i < 4; i++)
        tile[ty + i * 8][tx] = W[(by + ty + i * 8) * D + bx + tx];
    __syncthreads();
#pragma unroll
    for (int i = 0; i < 4; i++) {
        const int n = bx + ty + i * 8;
        const int k = by + tx;
        g_wt[n * D + k] = __float2half_rn(tile[tx][ty + i * 8]);
    }
}

// ---------------------------------------------------------------------------
// Kernel 1: weighted gather over fp16 features -> x fp16.
// 128 threads = 4 nodes x 32 threads; thread owns 8 columns (one uint4).
// ---------------------------------------------------------------------------
__global__ __launch_bounds__(128) void gather_kernel(
    const int* __restrict__ neighbors,     // int32 (JAX x64-off downcast)
    const float* __restrict__ weights)
{
    __shared__ float sw[4][K_NBR];
    __shared__ int   sn[4][K_NBR];
    const int tid   = threadIdx.x;
    const int node4 = blockIdx.x * 4;

    if (tid < 64) {
        const int nl = tid >> 4, kk = tid & 15;
        const int gn = node4 + nl;
        float w = 0.f; int nb = 0;
        if (gn < N_NODES) {
            w  = weights[gn * K_NBR + kk];
            nb = neighbors[gn * K_NBR + kk];
        }
        sw[nl][kk] = w;
        sn[nl][kk] = nb;
    }
    __syncthreads();
    if (tid < 4) {
        float ws = 0.f;
#pragma unroll
        for (int k = 0; k < K_NBR; k++) ws += sw[tid][k];
        const bool z = (ws == 0.f);
        const float inv = z ? 0.f : 1.f / ws;
#pragma unroll
        for (int k = 0; k < K_NBR; k++)
            sw[tid][k] = z ? (1.f / (float)K_NBR) : sw[tid][k] * inv;
    }
    __syncthreads();

    const int nl = tid >> 5;     // node within block
    const int t  = tid & 31;     // uint4 lane (8 halves)
    const int node = node4 + nl;
    if (node >= N_NODES) return;

    const uint4* __restrict__ f4 = (const uint4*)g_fh;
    float2 acc[4] = {{0.f, 0.f}, {0.f, 0.f}, {0.f, 0.f}, {0.f, 0.f}};

#pragma unroll
    for (int k = 0; k < K_NBR; k++) {
        const float w = sw[nl][k];
        const uint4 v = f4[(size_t)sn[nl][k] * 32 + t];
        float2 f;
        f = u2f2(v.x); acc[0].x += w * f.x; acc[0].y += w * f.y;
        f = u2f2(v.y); acc[1].x += w * f.x; acc[1].y += w * f.y;
        f = u2f2(v.z); acc[2].x += w * f.x; acc[2].y += w * f.y;
        f = u2f2(v.w); acc[3].x += w * f.x; acc[3].y += w * f.y;
    }

    uint4 o;
    o.x = f2u(acc[0].x, acc[0].y);
    o.y = f2u(acc[1].x, acc[1].y);
    o.z = f2u(acc[2].x, acc[2].y);
    o.w = f2u(acc[3].x, acc[3].y);
    ((uint4*)g_x)[(size_t)node * 32 + t] = o;
}

// ---------------------------------------------------------------------------
// Kernel 2: 1-term fp16 mma GEMM (fp32 accum) + fused LayerNorm.
// 512 threads = 16 warps (4 row x 4 col), warp tile 32m x 64n, CTA 128 x 256.
// 4 warps/SMSP to hide ldsm->mma latency (R12 showed issue=19%, latency-bound
// at 2 warps/SMSP). Full K resident; 4 commit groups, decreasing wait_group.
// ---------------------------------------------------------------------------
__global__ __launch_bounds__(512, 1) void gemm_ln(
    const float* __restrict__ bias,
    const float* __restrict__ gamma,
    const float* __restrict__ beta,
    float* __restrict__ out)
{
    extern __shared__ char smem[];
    const uint32_t su = smem_to_u32(smem);
    const int tid  = threadIdx.x;
    const int warp = tid >> 5;
    const int lid  = tid & 31;
    const int wr   = warp >> 2;   // 0..3 : rows wr*32..+31
    const int wc   = warp & 3;    // 0..3 : cols wc*64..+63
    const int grp  = lid >> 3;
    const int idx  = lid & 7;
    const int rb   = blockIdx.x * MROWS;

    // issue ALL loads up front: per chunk c one commit group (A[c] + B[c])
    for (int c = 0; c < 4; c++) {
#pragma unroll
        for (int i = 0; i < 2; i++) {            // A: 128 rows x 8 x 16B = 1024
            const int e = i * 512 + tid;
            const int row = e >> 3, u = e & 7;
            const uint32_t dst = su + OFF_A(c)
                + ((uint32_t)(row * 128 + u * 16) ^ (uint32_t)((row & 7) * 16));
            const int gr = rb + row;
            const int sz = (gr < N_NODES) ? 16 : 0;
            CP_ASYNC16(dst, (const char*)&g_x[(size_t)gr * D + c * 64 + u * 8], sz);
        }
#pragma unroll
        for (int i = 0; i < 4; i++) {            // B: 256 n x 8 x 16B = 2048
            const int e = i * 512 + tid;
            const int n = e >> 3, u = e & 7;
            const uint32_t dst = su + OFF_B(c)
                + ((uint32_t)(n * 128 + u * 16) ^ (uint32_t)((n & 7) * 16));
            CP_ASYNC16(dst, (const char*)&g_wt[(size_t)n * D + c * 64 + u * 8], 16);
        }
        CP_COMMIT();
    }

    // params
    if (tid < D) {
        ((float*)(smem + OFF_BIAS))[tid]  = bias[tid];
        ((float*)(smem + OFF_GAMMA))[tid] = gamma[tid];
        ((float*)(smem + OFF_BETA))[tid]  = beta[tid];
    }

    float acc[2][8][4];
#pragma unroll
    for (int mt = 0; mt < 2; mt++)
#pragma unroll
        for (int nt = 0; nt < 8; nt++)
#pragma unroll
            for (int q = 0; q < 4; q++) acc[mt][nt][q] = 0.f;

    const int a_kh = grp >> 1;
    uint32_t a_base[2];
#pragma unroll
    for (int mt = 0; mt < 2; mt++)
        a_base[mt] = (uint32_t)((wr * 32 + mt * 16 + (grp & 1) * 8 + idx) * 128);
    const int b_kh = grp & 1;
    uint32_t b_base[4];
#pragma unroll
    for (int p = 0; p < 4; p++)
        b_base[p] = (uint32_t)((wc * 64 + p * 16 + (grp >> 1) * 8 + idx) * 128);
    const uint32_t xorv = (uint32_t)(idx * 16);

    // compute phase: chunk c ready when <= (3-c) groups pending
#pragma unroll
    for (int c = 0; c < 4; c++) {
        if (c == 0)      CP_WAIT(3);
        else if (c == 1) CP_WAIT(2);
        else if (c == 2) CP_WAIT(1);
        else             CP_WAIT(0);
        __syncthreads();

        const uint32_t abase = su + OFF_A(c);
        const uint32_t bbase = su + OFF_B(c);

#pragma unroll
        for (int ks = 0; ks < 4; ks++) {
            const uint32_t xa = ((uint32_t)(ks * 32 + a_kh * 16)) ^ xorv;
            const uint32_t xb = ((uint32_t)(ks * 32 + b_kh * 16)) ^ xorv;

            uint32_t ah[2][4];
#pragma unroll
            for (int mt = 0; mt < 2; mt++)
                LDSM_X4(ah[mt], abase + a_base[mt] + xa);
#pragma unroll
            for (int p = 0; p < 4; p++) {
                uint32_t bh[4];
                LDSM_X4(bh, bbase + b_base[p] + xb);
#pragma unroll
                for (int h = 0; h < 2; h++) {
                    const int nt = p * 2 + h;
                    const uint32_t b0 = bh[h * 2], b1 = bh[h * 2 + 1];
#pragma unroll
                    for (int mt = 0; mt < 2; mt++)
                        mma16816(acc[mt][nt], ah[mt], b0, b1);
                }
            }
        }
    }
    __syncthreads();

    // ---- epilogue: bias + LayerNorm + affine ----
    const float* bias_s  = (const float*)(smem + OFF_BIAS);
    const float* gamma_s = (const float*)(smem + OFF_GAMMA);
    const float* beta_s  = (const float*)(smem + OFF_BETA);
    float2* red  = (float2*)(smem + OFF_RED);    // red[row*4 + wc]
    float2* stat = (float2*)(smem + OFF_STAT);

#pragma unroll
    for (int mt = 0; mt < 2; mt++)
#pragma unroll
        for (int nt = 0; nt < 8; nt++) {
            const int col = wc * 64 + nt * 8 + (lid & 3) * 2;
            acc[mt][nt][0] += bias_s[col];
            acc[mt][nt][1] += bias_s[col + 1];
            acc[mt][nt][2] += bias_s[col];
            acc[mt][nt][3] += bias_s[col + 1];
        }

    float s1[4], s2[4];
#pragma unroll
    for (int mt = 0; mt < 2; mt++) {
        float a1 = 0.f, a2 = 0.f, b1 = 0.f, b2 = 0.f;
#pragma unroll
        for (int nt = 0; nt < 8; nt++) {
            a1 += acc[mt][nt][0] + acc[mt][nt][1];
            a2 += acc[mt][nt][0] * acc[mt][nt][0] + acc[mt][nt][1] * acc[mt][nt][1];
            b1 += acc[mt][nt][2] + acc[mt][nt][3];
            b2 += acc[mt][nt][2] * acc[mt][nt][2] + acc[mt][nt][3] * acc[mt][nt][3];
        }
        s1[mt * 2] = a1;     s2[mt * 2] = a2;
        s1[mt * 2 + 1] = b1; s2[mt * 2 + 1] = b2;
    }
#pragma unroll
    for (int z = 1; z <= 2; z <<= 1)
#pragma unroll
        for (int i = 0; i < 4; i++) {
            s1[i] += __shfl_xor_sync(0xffffffffu, s1[i], z);
            s2[i] += __shfl_xor_sync(0xffffffffu, s2[i], z);
        }

    if ((lid & 3) == 0) {
        const int g = lid >> 2;
#pragma unroll
        for (int mt = 0; mt < 2; mt++)
#pragma unroll
            for (int h = 0; h < 2; h++) {
                const int row = wr * 32 + mt * 16 + h * 8 + g;
                red[row * 4 + wc] = make_float2(s1[mt * 2 + h], s2[mt * 2 + h]);
            }
    }
    __syncthreads();

    if (tid < MROWS) {
        float t1 = 0.f, t2 = 0.f;
#pragma unroll
        for (int w = 0; w < 4; w++) {
            const float2 v = red[tid * 4 + w];
            t1 += v.x; t2 += v.y;
        }
        const float mean = t1 * (1.f / (float)D);
        const float var  = t2 * (1.f / (float)D) - mean * mean;
        stat[tid] = make_float2(mean, rsqrtf(var + LN_EPS));
    }
    __syncthreads();

    const int g = lid >> 2;
#pragma unroll
    for (int mt = 0; mt < 2; mt++) {
        const int r0 = wr * 32 + mt * 16 + g;
        const int r1 = r0 + 8;
        const float2 st0 = stat[r0];
        const float2 st1 = stat[r1];
#pragma unroll
        for (int nt = 0; nt < 8; nt++) {
            const int col = wc * 64 + nt * 8 + (lid & 3) * 2;
            const float gm0 = gamma_s[col], gm1 = gamma_s[col + 1];
            const float bt0 = beta_s[col],  bt1 = beta_s[col + 1];
            if (rb + r0 < N_NODES) {
                float2 o;
                o.x = (acc[mt][nt][0] - st0.x) * st0.y * gm0 + bt0;
                o.y = (acc[mt][nt][1] - st0.x) * st0.y * gm1 + bt1;
                *(float2*)&out[(size_t)(rb + r0) * D + col] = o;
            }
            if (rb + r1 < N_NODES) {
                float2 o;
                o.x = (acc[mt][nt][2] - st1.x) * st1.y * gm0 + bt0;
                o.y = (acc[mt][nt][3] - st1.x) * st1.y * gm1 + bt1;
                *(float2*)&out[(size_t)(rb + r1) * D + col] = o;
            }
        }
    }
}

// ---------------------------------------------------------------------------
// Launch
// ---------------------------------------------------------------------------
extern "C" void kernel_launch(void* const* d_in, const int* in_sizes, int n_in,
                              void* d_out, int out_size)
{
    const float* features  = (const float*)d_in[0];
    const int*   neighbors = (const int*)d_in[1];
    const float* weights   = (const float*)d_in[2];
    const float* W         = (const float*)d_in[3];
    const float* bias      = (const float*)d_in[4];
    const float* gamma     = (const float*)d_in[5];
    const float* beta      = (const float*)d_in[6];
    float*       out       = (float*)d_out;

    cudaFuncSetAttribute(gemm_ln,
                         cudaFuncAttributeMaxDynamicSharedMemorySize, SMEM_TOTAL);

    prep_all<<<FEAT_BLOCKS + 64, 256>>>(features, W);
    gather_kernel<<<(N_NODES + 3) / 4, 128>>>(neighbors, weights);
    gemm_ln<<<NBLOCKS, 512, SMEM_TOTAL>>>(bias, gamma, beta, out);
}